// round 2
// baseline (speedup 1.0000x reference)
#include <cuda_runtime.h>

#define BATCH 256
#define NROWS 256
#define MCOLS 256
#define DDIM  32
#define TPB   128          // NROWS / 2 threads per batch (2 rows per thread)
#define BIGF  1e8f

__device__ float g_part[BATCH];

typedef unsigned long long u64;

// packed fp32x2 FMA: d.lo += a.lo*b.lo ; d.hi += a.hi*b.hi   (sm_100+ only via PTX)
#define FMA_F32X2(d, a, b) \
    asm("fma.rn.f32x2 %0, %1, %2, %0;" : "+l"(d) : "l"(a), "l"(b))

#define PACK_F32X2(out, lo, hi) \
    asm("mov.b64 %0, {%1, %2};" : "=l"(out) : "f"(lo), "f"(hi))

#define UNPACK_F32X2(lo, hi, in) \
    asm("mov.b64 {%0, %1}, %2;" : "=f"(lo), "=f"(hi) : "l"(in))

__device__ __forceinline__ float softmin3(float a, float b, float c) {
    float mn = fminf(fminf(a, b), c);
    float s  = __expf(mn - a) + __expf(mn - b) + __expf(mn - c);
    return mn - __logf(s);
}

__global__ __launch_bounds__(TPB)
void sdtw_kernel(const float* __restrict__ X, const float* __restrict__ Y) {
    // y stored as float4 chunks, transposed-by-chunk: sy4[c][j], pad 257 to kill bank conflicts
    __shared__ float4 sy4[8 * 257];
    __shared__ float  sy2[MCOLS];
    __shared__ float  bot[2][TPB];

    const int t = threadIdx.x;
    const int b = blockIdx.x;
    const float* xb = X + (size_t)b * NROWS * DDIM;
    const float* yb = Y + (size_t)b * MCOLS * DDIM;

    // ---- stage y into SMEM (chunk-transposed), coalesced global reads ----
    const float4* yb4 = (const float4*)yb;
    for (int k = t; k < MCOLS * 8; k += TPB) {
        int j = k >> 3, c = k & 7;
        sy4[c * 257 + j] = yb4[k];
    }
    // ---- y squared norms ----
    for (int j = t; j < MCOLS; j += TPB) {
        const float4* row = (const float4*)(yb + j * DDIM);
        float acc = 0.f;
        #pragma unroll
        for (int c = 0; c < 8; c++) {
            float4 v = row[c];
            acc += v.x * v.x + v.y * v.y + v.z * v.z + v.w * v.w;
        }
        sy2[j] = acc;
    }

    // ---- load this thread's 2 x-rows into registers, packed as f32x2 pairs ----
    u64 ax0[16], ax1[16];
    float xx0 = 0.f, xx1 = 0.f;
    {
        const float4* r0 = (const float4*)(xb + (size_t)(2 * t)     * DDIM);
        const float4* r1 = (const float4*)(xb + (size_t)(2 * t + 1) * DDIM);
        #pragma unroll
        for (int c = 0; c < 8; c++) {
            float4 v0 = r0[c], v1 = r1[c];
            PACK_F32X2(ax0[2*c],     v0.x, v0.y);
            PACK_F32X2(ax0[2*c + 1], v0.z, v0.w);
            PACK_F32X2(ax1[2*c],     v1.x, v1.y);
            PACK_F32X2(ax1[2*c + 1], v1.z, v1.w);
            xx0 += v0.x * v0.x + v0.y * v0.y + v0.z * v0.z + v0.w * v0.w;
            xx1 += v1.x * v1.x + v1.y * v1.y + v1.z * v1.z + v1.w * v1.w;
        }
    }
    __syncthreads();

    // ---- DP state in registers ----
    // left0 = D[base+1][j-1], left1 = D[base+2][j-1], tl = D[base][j-1]  (base = 2t, 1-based DP rows)
    float left0 = BIGF, left1 = BIGF;
    float tl = (t == 0) ? 0.f : BIGF;

    const int STEPS = MCOLS + TPB - 1;   // 383
    for (int s = 0; s < STEPS; s++) {
        int jj = s - t;                  // 0-based y column
        if (jj >= 0 && jj < MCOLS) {
            // up0 = D[base][j] from neighbor thread's bottom row (prev step), row-0 boundary = BIG
            float up0 = BIGF;
            if (t > 0) up0 = bot[(s & 1) ^ 1][t - 1];

            // packed-f32x2 dot products over k for both rows (2 acc chains/row for ILP)
            u64 a0 = 0ull, b0 = 0ull, a1 = 0ull, b1 = 0ull;
            #pragma unroll
            for (int c = 0; c < 8; c++) {
                float4 ya = sy4[c * 257 + jj];
                u64 ylo, yhi;
                PACK_F32X2(ylo, ya.x, ya.y);
                PACK_F32X2(yhi, ya.z, ya.w);
                FMA_F32X2(a0, ax0[2*c],     ylo);
                FMA_F32X2(b0, ax0[2*c + 1], yhi);
                FMA_F32X2(a1, ax1[2*c],     ylo);
                FMA_F32X2(b1, ax1[2*c + 1], yhi);
            }
            float l0, h0, l1, h1, l0b, h0b, l1b, h1b;
            UNPACK_F32X2(l0, h0, a0);
            UNPACK_F32X2(l0b, h0b, b0);
            UNPACK_F32X2(l1, h1, a1);
            UNPACK_F32X2(l1b, h1b, b1);
            float dot0 = (l0 + h0) + (l0b + h0b);
            float dot1 = (l1 + h1) + (l1b + h1b);

            float yy   = sy2[jj];
            float dist0 = fmaxf(fmaf(-2.f, dot0, xx0 + yy), 0.f);
            float dist1 = fmaxf(fmaf(-2.f, dot1, xx1 + yy), 0.f);

            // serial 2-cell softmin chain (all register-resident)
            float v0 = dist0 + softmin3(up0, left0, tl);
            float v1 = dist1 + softmin3(v0,  left1, left0);
            tl = up0; left0 = v0; left1 = v1;

            bot[s & 1][t] = v1;
            if (t == TPB - 1 && jj == MCOLS - 1) g_part[b] = v1;  // D[N][M]
        }
        __syncthreads();
    }
}

__global__ void reduce_kernel(float* __restrict__ out) {
    __shared__ float s[BATCH];
    int t = threadIdx.x;
    s[t] = g_part[t];
    __syncthreads();
    for (int o = BATCH / 2; o > 0; o >>= 1) {
        if (t < o) s[t] += s[t + o];
        __syncthreads();
    }
    if (t == 0) out[0] = s[0] / (float)BATCH;
}

extern "C" void kernel_launch(void* const* d_in, const int* in_sizes, int n_in,
                              void* d_out, int out_size) {
    const float* x = (const float*)d_in[0];
    const float* y = (const float*)d_in[1];
    float* out = (float*)d_out;
    sdtw_kernel<<<BATCH, TPB>>>(x, y);
    reduce_kernel<<<1, BATCH>>>(out);
}